// round 8
// baseline (speedup 1.0000x reference)
#include <cuda_runtime.h>
#include <cstdint>

#define TPB  256       // threads per block (2 per cell)
#define CPT  128       // cells per tile
#define DD   30        // features per cell: B*5 + C
#define LAMBDA_NOOBJ 0.5f
#define NSTAGE 3

#define TILE_FLOATS (CPT * DD)            // 3840 floats per array per tile
#define TILE_BYTES  (TILE_FLOATS * 4)     // 15360 B
// dynamic smem: [ sp0|st0 | sp1|st1 | sp2|st2 | full[3] ]
#define SMEM_DYN_BYTES (NSTAGE * 2 * TILE_BYTES + NSTAGE * 8)

__device__ double       g_acc;
__device__ unsigned int g_count;

__device__ __forceinline__ uint32_t smem_u32(const void* p) {
    uint32_t a;
    asm("{ .reg .u64 t; cvta.to.shared.u64 t, %1; cvt.u32.u64 %0, t; }"
        : "=r"(a) : "l"(p));
    return a;
}

__device__ __forceinline__ void mbar_wait(uint32_t mb, uint32_t parity) {
    uint32_t done;
    do {
        asm volatile(
            "{\n\t.reg .pred p;\n\t"
            "mbarrier.try_wait.parity.acquire.cta.shared::cta.b64 p, [%1], %2, 0x989680;\n\t"
            "selp.b32 %0, 1, 0, p;\n\t}"
            : "=r"(done) : "r"(mb), "r"(parity) : "memory");
    } while (!done);
}

__device__ __forceinline__ void issue_tile_copy(uint32_t mb_full,
                                                uint32_t sp_addr, uint32_t st_addr,
                                                const float* preds, const float* targets,
                                                long long tile)
{
    asm volatile("mbarrier.arrive.expect_tx.shared.b64 _, [%0], %1;"
                 :: "r"(mb_full), "r"(2u * TILE_BYTES) : "memory");
    asm volatile("cp.async.bulk.shared::cta.global.mbarrier::complete_tx::bytes "
                 "[%0], [%1], %2, [%3];"
                 :: "r"(sp_addr), "l"(preds + tile * CPT * DD),
                    "r"((uint32_t)TILE_BYTES), "r"(mb_full) : "memory");
    asm volatile("cp.async.bulk.shared::cta.global.mbarrier::complete_tx::bytes "
                 "[%0], [%1], %2, [%3];"
                 :: "r"(st_addr), "l"(targets + tile * CPT * DD),
                    "r"((uint32_t)TILE_BYTES), "r"(mb_full) : "memory");
}

// Pair-split cell loss: lanes (2k, 2k+1) cooperate on cell k. Uniform control
// flow; returns this thread's ADDITIVE contribution.
__device__ __forceinline__ float cell_loss_pair(const float* __restrict__ p,
                                                const float* __restrict__ t,
                                                int half)
{
    const int bo = half * 5;
    const float x1 = p[bo+0], y1 = p[bo+1], w1 = p[bo+2], h1 = p[bo+3];
    const float x2 = t[bo+0], y2 = t[bo+1], w2 = t[bo+2], h2 = t[bo+3];
    const float tlx = fmaxf(x1 - w1 * 0.5f, x2 - w2 * 0.5f);
    const float tly = fmaxf(y1 - h1 * 0.5f, y2 - h2 * 0.5f);
    const float brx = fminf(x1 + w1 * 0.5f, x2 + w2 * 0.5f);
    const float bry = fminf(y1 + h1 * 0.5f, y2 + h2 * 0.5f);
    const float iw = fmaxf(0.0f, brx - tlx);
    const float ih = fmaxf(0.0f, bry - tly);
    const float inter = iw * ih;
    const float iou_own = inter / (w1 * h1 + w2 * h2 - inter);

    const float iou_peer = __shfl_xor_sync(0xffffffffu, iou_own, 1);
    const float iou0 = half ? iou_peer : iou_own;
    const float iou1 = half ? iou_own  : iou_peer;
    const int bi = (iou1 > iou0) ? 1 : 0;          // first-max tie break

    const int cb = 10 + half * 10;
    float cls = 0.0f;
    float m = t[cb];
    int g = half * 10;
    int has = 0;
    #pragma unroll
    for (int j = 0; j < 10; j++) {
        const float pc = p[cb + j];
        const float tc = t[cb + j];
        const float d = pc - tc;
        cls += d * d;
        has |= (tc != 0.0f) ? 1 : 0;
        if (tc > m) { m = tc; g = half * 10 + j; }
    }
    const float pm  = __shfl_xor_sync(0xffffffffu, m, 1);
    const int   pkt = __shfl_xor_sync(0xffffffffu, g | (has << 8), 1);
    const int  peer_g   = pkt & 0xff;
    const int  peer_has = pkt >> 8;
    const bool has_obj  = ((has | peer_has) & 1) != 0;

    const float m0 = half ? pm : m;   const int g0 = half ? peer_g : g;
    const float m1 = half ? m  : pm;  const int g1 = half ? g : peer_g;
    const int gnd = (m1 > m0) ? g1 : g0;           // lower index wins ties
    const float pg = p[10 + gnd];

    float pos_h = 0.0f;
    if (bi == half && has_obj) {
        const float dx = p[bo+0] - t[bo+0];
        const float dy = p[bo+1] - t[bo+1];
        pos_h = dx * dx + dy * dy;
    }

    const float cd = iou_own * pg - iou_own;
    const float w  = (bi == half) ? 1.0f : LAMBDA_NOOBJ;
    return cls + w * cd * cd + pos_h;
}

// full scalar cell loss (tail path only; unused for these shapes)
__device__ __forceinline__ float cell_loss_full(const float* p, const float* t)
{
    float iou[2];
    #pragma unroll
    for (int b = 0; b < 2; b++) {
        const float x1 = p[b*5+0], y1 = p[b*5+1], w1 = p[b*5+2], h1 = p[b*5+3];
        const float x2 = t[b*5+0], y2 = t[b*5+1], w2 = t[b*5+2], h2 = t[b*5+3];
        const float tlx = fmaxf(x1 - w1 * 0.5f, x2 - w2 * 0.5f);
        const float tly = fmaxf(y1 - h1 * 0.5f, y2 - h2 * 0.5f);
        const float brx = fminf(x1 + w1 * 0.5f, x2 + w2 * 0.5f);
        const float bry = fminf(y1 + h1 * 0.5f, y2 + h2 * 0.5f);
        const float iw = fmaxf(0.0f, brx - tlx);
        const float ih = fmaxf(0.0f, bry - tly);
        const float inter = iw * ih;
        iou[b] = inter / (w1 * h1 + w2 * h2 - inter);
    }
    const int bi = (iou[1] > iou[0]) ? 1 : 0;
    float cls = 0.0f, maxtc = t[10];
    int gnd = 0; bool has_obj = false;
    #pragma unroll
    for (int j = 0; j < 20; j++) {
        const float pc = p[10 + j], tc = t[10 + j];
        const float d = pc - tc;
        cls += d * d;
        if (tc != 0.0f) has_obj = true;
        if (tc > maxtc) { maxtc = tc; gnd = j; }
    }
    const float pg = p[10 + gnd];
    const float dx = p[bi*5+0] - t[bi*5+0];
    const float dy = p[bi*5+1] - t[bi*5+1];
    const float pos = has_obj ? (dx * dx + dy * dy) : 0.0f;
    float conf = 0.0f;
    #pragma unroll
    for (int b = 0; b < 2; b++) {
        const float cd = iou[b] * pg - iou[b];
        const float w  = (b == bi) ? 1.0f : LAMBDA_NOOBJ;
        conf += w * cd * cd;
    }
    return pos + cls + conf;
}

__global__ __launch_bounds__(TPB) void yolo_loss_kernel(
    const float* __restrict__ preds,
    const float* __restrict__ targets,
    long long n_cells,
    unsigned int n_blocks,
    float invN,
    float* __restrict__ out)
{
    extern __shared__ __align__(128) float smem[];
    uint32_t sp_a[NSTAGE], st_a[NSTAGE], full_a[NSTAGE];
    {
        uint64_t* bars = reinterpret_cast<uint64_t*>(smem + NSTAGE * 2 * TILE_FLOATS);
        #pragma unroll
        for (int s = 0; s < NSTAGE; s++) {
            sp_a[s]   = smem_u32(smem + (2 * s)     * TILE_FLOATS);
            st_a[s]   = smem_u32(smem + (2 * s + 1) * TILE_FLOATS);
            full_a[s] = smem_u32(&bars[s]);
        }
    }

    const int tid  = threadIdx.x;
    const int cell = tid >> 1;          // 0..127
    const int half = tid & 1;
    const unsigned int bid  = blockIdx.x;
    const unsigned int grid = gridDim.x;

    const unsigned int num_full = (unsigned int)(n_cells / CPT);
    const unsigned int my_count =
        (num_full > bid) ? (num_full - 1u - bid) / grid + 1u : 0u;

    if (tid == 0) {
        #pragma unroll
        for (int s = 0; s < NSTAGE; s++)
            asm volatile("mbarrier.init.shared.b64 [%0], %1;"
                         :: "r"(full_a[s]), "r"(1u) : "memory");
        asm volatile("fence.proxy.async.shared::cta;" ::: "memory");
        const unsigned int pro = my_count < NSTAGE ? my_count : NSTAGE;
        for (unsigned int s = 0; s < pro; s++)
            issue_tile_copy(full_a[s], sp_a[s], st_a[s], preds, targets,
                            (long long)(bid + s * grid));
    }
    __syncthreads();   // barrier inits visible before anyone waits

    float loss = 0.0f;

    for (unsigned int j = 0; j < my_count; j++) {
        const unsigned int stage = j % NSTAGE;
        const uint32_t par = (j / NSTAGE) & 1u;

        mbar_wait(full_a[stage], par);

        loss += cell_loss_pair(
            reinterpret_cast<const float*>(smem) + (2 * stage)     * TILE_FLOATS + cell * DD,
            reinterpret_cast<const float*>(smem) + (2 * stage + 1) * TILE_FLOATS + cell * DD,
            half);

        __syncthreads();   // everyone done reading this stage's buffers

        // refill this stage with tile j+NSTAGE
        if (tid == 0 && j + NSTAGE < my_count)
            issue_tile_copy(full_a[stage], sp_a[stage], st_a[stage], preds, targets,
                            (long long)(bid + (j + NSTAGE) * grid));
    }

    // tail cells (n_cells % CPT) — block 0, direct gmem reads, scalar path
    const long long tail_start = (long long)num_full * CPT;
    if (bid == 0 && tail_start + tid < n_cells) {
        loss += cell_loss_full(preds   + (tail_start + tid) * DD,
                               targets + (tail_start + tid) * DD);
    }

    // block reduction: warp shuffle -> smem -> one double atomic per block
    #pragma unroll
    for (int o = 16; o > 0; o >>= 1)
        loss += __shfl_down_sync(0xffffffffu, loss, o);

    __shared__ float wsum[TPB / 32];
    __shared__ bool  is_last;
    if ((tid & 31) == 0) wsum[tid >> 5] = loss;
    __syncthreads();

    if (tid == 0) {
        float s = 0.0f;
        #pragma unroll
        for (int i = 0; i < TPB / 32; i++) s += wsum[i];
        atomicAdd(&g_acc, (double)s);
        __threadfence();
        const unsigned int prev = atomicAdd(&g_count, 1u);
        is_last = (prev == n_blocks - 1u);
    }
    __syncthreads();

    if (is_last && tid == 0) {
        out[0] = (float)(g_acc * (double)invN);
        g_acc   = 0.0;                // reset for next graph replay
        __threadfence();
        g_count = 0u;
    }
}

extern "C" void kernel_launch(void* const* d_in, const int* in_sizes, int n_in,
                              void* d_out, int out_size)
{
    const float* preds   = (const float*)d_in[0];
    const float* targets = (const float*)d_in[1];

    const long long n_cells = (long long)in_sizes[0] / DD;   // N*S*S
    const long long N = n_cells / 49;                         // S=7

    cudaFuncSetAttribute(yolo_loss_kernel,
                         cudaFuncAttributeMaxDynamicSharedMemorySize,
                         SMEM_DYN_BYTES);

    const unsigned int num_tiles = (unsigned int)((n_cells + CPT - 1) / CPT);
    unsigned int grid = 148u * 2u;            // 2 blocks/SM (~92 KB smem each)
    if (grid > num_tiles) grid = num_tiles ? num_tiles : 1u;

    yolo_loss_kernel<<<grid, TPB, SMEM_DYN_BYTES>>>(preds, targets, n_cells, grid,
                                                    1.0f / (float)N, (float*)d_out);
}

// round 10
// speedup vs baseline: 1.0091x; 1.0091x over previous
#include <cuda_runtime.h>
#include <cstdint>

#define TPB  512       // threads per block (2 per cell)
#define CPT  256       // cells per tile
#define DD   30        // features per cell: B*5 + C
#define LAMBDA_NOOBJ 0.5f
#define NSTAGE 3

#define TILE_FLOATS (CPT * DD)            // 7680 floats per array per tile
#define TILE_BYTES  (TILE_FLOATS * 4)     // 30720 B
// dynamic smem: [ sp0|st0 | sp1|st1 | sp2|st2 | full[3] ]
#define SMEM_DYN_BYTES (NSTAGE * 2 * TILE_BYTES + NSTAGE * 8)

__device__ double       g_acc;
__device__ unsigned int g_count;

__device__ __forceinline__ uint32_t smem_u32(const void* p) {
    uint32_t a;
    asm("{ .reg .u64 t; cvta.to.shared.u64 t, %1; cvt.u32.u64 %0, t; }"
        : "=r"(a) : "l"(p));
    return a;
}

__device__ __forceinline__ void mbar_wait(uint32_t mb, uint32_t parity) {
    uint32_t done;
    do {
        asm volatile(
            "{\n\t.reg .pred p;\n\t"
            "mbarrier.try_wait.parity.acquire.cta.shared::cta.b64 p, [%1], %2, 0x989680;\n\t"
            "selp.b32 %0, 1, 0, p;\n\t}"
            : "=r"(done) : "r"(mb), "r"(parity) : "memory");
    } while (!done);
}

__device__ __forceinline__ void issue_tile_copy(uint32_t mb_full,
                                                uint32_t sp_addr, uint32_t st_addr,
                                                const float* preds, const float* targets,
                                                long long tile)
{
    asm volatile("mbarrier.arrive.expect_tx.shared.b64 _, [%0], %1;"
                 :: "r"(mb_full), "r"(2u * TILE_BYTES) : "memory");
    asm volatile("cp.async.bulk.shared::cta.global.mbarrier::complete_tx::bytes "
                 "[%0], [%1], %2, [%3];"
                 :: "r"(sp_addr), "l"(preds + tile * CPT * DD),
                    "r"((uint32_t)TILE_BYTES), "r"(mb_full) : "memory");
    asm volatile("cp.async.bulk.shared::cta.global.mbarrier::complete_tx::bytes "
                 "[%0], [%1], %2, [%3];"
                 :: "r"(st_addr), "l"(targets + tile * CPT * DD),
                    "r"((uint32_t)TILE_BYTES), "r"(mb_full) : "memory");
}

// Pair-split cell loss: lanes (2k, 2k+1) cooperate on cell k. Uniform control
// flow; returns this thread's ADDITIVE contribution.
__device__ __forceinline__ float cell_loss_pair(const float* __restrict__ p,
                                                const float* __restrict__ t,
                                                int half)
{
    const int bo = half * 5;
    const float x1 = p[bo+0], y1 = p[bo+1], w1 = p[bo+2], h1 = p[bo+3];
    const float x2 = t[bo+0], y2 = t[bo+1], w2 = t[bo+2], h2 = t[bo+3];
    const float tlx = fmaxf(x1 - w1 * 0.5f, x2 - w2 * 0.5f);
    const float tly = fmaxf(y1 - h1 * 0.5f, y2 - h2 * 0.5f);
    const float brx = fminf(x1 + w1 * 0.5f, x2 + w2 * 0.5f);
    const float bry = fminf(y1 + h1 * 0.5f, y2 + h2 * 0.5f);
    const float iw = fmaxf(0.0f, brx - tlx);
    const float ih = fmaxf(0.0f, bry - tly);
    const float inter = iw * ih;
    const float iou_own = inter / (w1 * h1 + w2 * h2 - inter);

    const float iou_peer = __shfl_xor_sync(0xffffffffu, iou_own, 1);
    const float iou0 = half ? iou_peer : iou_own;
    const float iou1 = half ? iou_own  : iou_peer;
    const int bi = (iou1 > iou0) ? 1 : 0;          // first-max tie break

    const int cb = 10 + half * 10;
    float cls = 0.0f;
    float m = t[cb];
    int g = half * 10;
    int has = 0;
    #pragma unroll
    for (int j = 0; j < 10; j++) {
        const float pc = p[cb + j];
        const float tc = t[cb + j];
        const float d = pc - tc;
        cls += d * d;
        has |= (tc != 0.0f) ? 1 : 0;
        if (tc > m) { m = tc; g = half * 10 + j; }
    }
    const float pm  = __shfl_xor_sync(0xffffffffu, m, 1);
    const int   pkt = __shfl_xor_sync(0xffffffffu, g | (has << 8), 1);
    const int  peer_g   = pkt & 0xff;
    const int  peer_has = pkt >> 8;
    const bool has_obj  = ((has | peer_has) & 1) != 0;

    const float m0 = half ? pm : m;   const int g0 = half ? peer_g : g;
    const float m1 = half ? m  : pm;  const int g1 = half ? g : peer_g;
    const int gnd = (m1 > m0) ? g1 : g0;           // lower index wins ties
    const float pg = p[10 + gnd];

    float pos_h = 0.0f;
    if (bi == half && has_obj) {
        const float dx = p[bo+0] - t[bo+0];
        const float dy = p[bo+1] - t[bo+1];
        pos_h = dx * dx + dy * dy;
    }

    const float cd = iou_own * pg - iou_own;
    const float w  = (bi == half) ? 1.0f : LAMBDA_NOOBJ;
    return cls + w * cd * cd + pos_h;
}

// full scalar cell loss (tail path only; unused for these shapes)
__device__ __forceinline__ float cell_loss_full(const float* p, const float* t)
{
    float iou[2];
    #pragma unroll
    for (int b = 0; b < 2; b++) {
        const float x1 = p[b*5+0], y1 = p[b*5+1], w1 = p[b*5+2], h1 = p[b*5+3];
        const float x2 = t[b*5+0], y2 = t[b*5+1], w2 = t[b*5+2], h2 = t[b*5+3];
        const float tlx = fmaxf(x1 - w1 * 0.5f, x2 - w2 * 0.5f);
        const float tly = fmaxf(y1 - h1 * 0.5f, y2 - h2 * 0.5f);
        const float brx = fminf(x1 + w1 * 0.5f, x2 + w2 * 0.5f);
        const float bry = fminf(y1 + h1 * 0.5f, y2 + h2 * 0.5f);
        const float iw = fmaxf(0.0f, brx - tlx);
        const float ih = fmaxf(0.0f, bry - tly);
        const float inter = iw * ih;
        iou[b] = inter / (w1 * h1 + w2 * h2 - inter);
    }
    const int bi = (iou[1] > iou[0]) ? 1 : 0;
    float cls = 0.0f, maxtc = t[10];
    int gnd = 0; bool has_obj = false;
    #pragma unroll
    for (int j = 0; j < 20; j++) {
        const float pc = p[10 + j], tc = t[10 + j];
        const float d = pc - tc;
        cls += d * d;
        if (tc != 0.0f) has_obj = true;
        if (tc > maxtc) { maxtc = tc; gnd = j; }
    }
    const float pg = p[10 + gnd];
    const float dx = p[bi*5+0] - t[bi*5+0];
    const float dy = p[bi*5+1] - t[bi*5+1];
    const float pos = has_obj ? (dx * dx + dy * dy) : 0.0f;
    float conf = 0.0f;
    #pragma unroll
    for (int b = 0; b < 2; b++) {
        const float cd = iou[b] * pg - iou[b];
        const float w  = (b == bi) ? 1.0f : LAMBDA_NOOBJ;
        conf += w * cd * cd;
    }
    return pos + cls + conf;
}

__global__ __launch_bounds__(TPB) void yolo_loss_kernel(
    const float* __restrict__ preds,
    const float* __restrict__ targets,
    long long n_cells,
    unsigned int n_blocks,
    float invN,
    float* __restrict__ out)
{
    extern __shared__ __align__(128) float smem[];
    uint32_t sp_a[NSTAGE], st_a[NSTAGE], full_a[NSTAGE];
    {
        uint64_t* bars = reinterpret_cast<uint64_t*>(smem + NSTAGE * 2 * TILE_FLOATS);
        #pragma unroll
        for (int s = 0; s < NSTAGE; s++) {
            sp_a[s]   = smem_u32(smem + (2 * s)     * TILE_FLOATS);
            st_a[s]   = smem_u32(smem + (2 * s + 1) * TILE_FLOATS);
            full_a[s] = smem_u32(&bars[s]);
        }
    }

    const int tid  = threadIdx.x;
    const int cell = tid >> 1;          // 0..255
    const int half = tid & 1;
    const unsigned int bid  = blockIdx.x;
    const unsigned int grid = gridDim.x;

    const unsigned int num_full = (unsigned int)(n_cells / CPT);
    const unsigned int my_count =
        (num_full > bid) ? (num_full - 1u - bid) / grid + 1u : 0u;

    if (tid == 0) {
        #pragma unroll
        for (int s = 0; s < NSTAGE; s++)
            asm volatile("mbarrier.init.shared.b64 [%0], %1;"
                         :: "r"(full_a[s]), "r"(1u) : "memory");
        asm volatile("fence.proxy.async.shared::cta;" ::: "memory");
        const unsigned int pro = my_count < NSTAGE ? my_count : NSTAGE;
        for (unsigned int s = 0; s < pro; s++)
            issue_tile_copy(full_a[s], sp_a[s], st_a[s], preds, targets,
                            (long long)(bid + s * grid));
    }
    __syncthreads();   // barrier inits visible before anyone waits

    float loss = 0.0f;

    for (unsigned int j = 0; j < my_count; j++) {
        const unsigned int stage = j % NSTAGE;
        const uint32_t par = (j / NSTAGE) & 1u;

        mbar_wait(full_a[stage], par);

        loss += cell_loss_pair(
            reinterpret_cast<const float*>(smem) + (2 * stage)     * TILE_FLOATS + cell * DD,
            reinterpret_cast<const float*>(smem) + (2 * stage + 1) * TILE_FLOATS + cell * DD,
            half);

        __syncthreads();   // everyone done reading this stage's buffers

        // refill this stage with tile j+NSTAGE
        if (tid == 0 && j + NSTAGE < my_count)
            issue_tile_copy(full_a[stage], sp_a[stage], st_a[stage], preds, targets,
                            (long long)(bid + (j + NSTAGE) * grid));
    }

    // tail cells (n_cells % CPT) — block 0, direct gmem reads, scalar path
    const long long tail_start = (long long)num_full * CPT;
    if (bid == 0 && tail_start + tid < n_cells) {
        loss += cell_loss_full(preds   + (tail_start + tid) * DD,
                               targets + (tail_start + tid) * DD);
    }

    // block reduction: warp shuffle -> smem -> one double atomic per block
    #pragma unroll
    for (int o = 16; o > 0; o >>= 1)
        loss += __shfl_down_sync(0xffffffffu, loss, o);

    __shared__ float wsum[TPB / 32];
    __shared__ bool  is_last;
    if ((tid & 31) == 0) wsum[tid >> 5] = loss;
    __syncthreads();

    if (tid == 0) {
        float s = 0.0f;
        #pragma unroll
        for (int i = 0; i < TPB / 32; i++) s += wsum[i];
        atomicAdd(&g_acc, (double)s);
        __threadfence();
        const unsigned int prev = atomicAdd(&g_count, 1u);
        is_last = (prev == n_blocks - 1u);
    }
    __syncthreads();

    if (is_last && tid == 0) {
        out[0] = (float)(g_acc * (double)invN);
        g_acc   = 0.0;                // reset for next graph replay
        __threadfence();
        g_count = 0u;
    }
}

extern "C" void kernel_launch(void* const* d_in, const int* in_sizes, int n_in,
                              void* d_out, int out_size)
{
    const float* preds   = (const float*)d_in[0];
    const float* targets = (const float*)d_in[1];

    const long long n_cells = (long long)in_sizes[0] / DD;   // N*S*S
    const long long N = n_cells / 49;                         // S=7

    cudaFuncSetAttribute(yolo_loss_kernel,
                         cudaFuncAttributeMaxDynamicSharedMemorySize,
                         SMEM_DYN_BYTES);

    const unsigned int num_tiles = (unsigned int)((n_cells + CPT - 1) / CPT);
    unsigned int grid = 148u;                 // 1 block/SM (~184 KB smem each)
    if (grid > num_tiles) grid = num_tiles ? num_tiles : 1u;

    yolo_loss_kernel<<<grid, TPB, SMEM_DYN_BYTES>>>(preds, targets, n_cells, grid,
                                                    1.0f / (float)N, (float*)d_out);
}

// round 11
// speedup vs baseline: 1.0340x; 1.0246x over previous
#include <cuda_runtime.h>
#include <cstdint>

#define TPB  512       // threads per block (2 per cell)
#define CPT  256       // cells per tile
#define DD   30        // features per cell: B*5 + C
#define LAMBDA_NOOBJ 0.5f
#define NSTAGE 3

#define TILE_FLOATS (CPT * DD)            // 7680 floats per array per tile
#define TILE_BYTES  (TILE_FLOATS * 4)     // 30720 B
#define TILE_F4     (TILE_FLOATS / 4)     // 1920 float4 per array per tile
// dynamic smem: [ sp0|st0 | sp1|st1 | sp2|st2 | full[3] ]
#define SMEM_DYN_BYTES (NSTAGE * 2 * TILE_BYTES + NSTAGE * 8)

__device__ double       g_acc;
__device__ unsigned int g_count;

__device__ __forceinline__ uint32_t smem_u32(const void* p) {
    uint32_t a;
    asm("{ .reg .u64 t; cvta.to.shared.u64 t, %1; cvt.u32.u64 %0, t; }"
        : "=r"(a) : "l"(p));
    return a;
}

__device__ __forceinline__ void mbar_wait(uint32_t mb, uint32_t parity) {
    uint32_t done;
    do {
        asm volatile(
            "{\n\t.reg .pred p;\n\t"
            "mbarrier.try_wait.parity.acquire.cta.shared::cta.b64 p, [%1], %2, 0x989680;\n\t"
            "selp.b32 %0, 1, 0, p;\n\t}"
            : "=r"(done) : "r"(mb), "r"(parity) : "memory");
    } while (!done);
}

// preds tile via TMA bulk copy (one thread)
__device__ __forceinline__ void issue_preds_tma(uint32_t mb_full, uint32_t sp_addr,
                                                const float* preds, long long tile)
{
    asm volatile("mbarrier.arrive.expect_tx.shared.b64 _, [%0], %1;"
                 :: "r"(mb_full), "r"((uint32_t)TILE_BYTES) : "memory");
    asm volatile("cp.async.bulk.shared::cta.global.mbarrier::complete_tx::bytes "
                 "[%0], [%1], %2, [%3];"
                 :: "r"(sp_addr), "l"(preds + tile * (long long)TILE_FLOATS),
                    "r"((uint32_t)TILE_BYTES), "r"(mb_full) : "memory");
}

// targets tile via per-thread cp.async (LSU path). All TPB threads participate.
// 1920 float4 / 512 threads = 3.75 -> 4 rounds, last guarded.
__device__ __forceinline__ void issue_targets_cpasync(uint32_t st_addr,
                                                      const float* targets,
                                                      long long tile, int tid)
{
    const float4* src = reinterpret_cast<const float4*>(targets + tile * (long long)TILE_FLOATS);
    #pragma unroll
    for (int r = 0; r < 4; r++) {
        const int idx = tid + r * TPB;
        if (idx < TILE_F4) {
            const uint32_t dst = st_addr + idx * 16u;
            asm volatile("cp.async.cg.shared.global [%0], [%1], 16;"
                         :: "r"(dst), "l"(src + idx) : "memory");
        }
    }
}

// Pair-split cell loss: lanes (2k, 2k+1) cooperate on cell k. Uniform control
// flow; returns this thread's ADDITIVE contribution.
__device__ __forceinline__ float cell_loss_pair(const float* __restrict__ p,
                                                const float* __restrict__ t,
                                                int half)
{
    const int bo = half * 5;
    const float x1 = p[bo+0], y1 = p[bo+1], w1 = p[bo+2], h1 = p[bo+3];
    const float x2 = t[bo+0], y2 = t[bo+1], w2 = t[bo+2], h2 = t[bo+3];
    const float tlx = fmaxf(x1 - w1 * 0.5f, x2 - w2 * 0.5f);
    const float tly = fmaxf(y1 - h1 * 0.5f, y2 - h2 * 0.5f);
    const float brx = fminf(x1 + w1 * 0.5f, x2 + w2 * 0.5f);
    const float bry = fminf(y1 + h1 * 0.5f, y2 + h2 * 0.5f);
    const float iw = fmaxf(0.0f, brx - tlx);
    const float ih = fmaxf(0.0f, bry - tly);
    const float inter = iw * ih;
    const float iou_own = inter / (w1 * h1 + w2 * h2 - inter);

    const float iou_peer = __shfl_xor_sync(0xffffffffu, iou_own, 1);
    const float iou0 = half ? iou_peer : iou_own;
    const float iou1 = half ? iou_own  : iou_peer;
    const int bi = (iou1 > iou0) ? 1 : 0;          // first-max tie break

    const int cb = 10 + half * 10;
    float cls = 0.0f;
    float m = t[cb];
    int g = half * 10;
    int has = 0;
    #pragma unroll
    for (int j = 0; j < 10; j++) {
        const float pc = p[cb + j];
        const float tc = t[cb + j];
        const float d = pc - tc;
        cls += d * d;
        has |= (tc != 0.0f) ? 1 : 0;
        if (tc > m) { m = tc; g = half * 10 + j; }
    }
    const float pm  = __shfl_xor_sync(0xffffffffu, m, 1);
    const int   pkt = __shfl_xor_sync(0xffffffffu, g | (has << 8), 1);
    const int  peer_g   = pkt & 0xff;
    const int  peer_has = pkt >> 8;
    const bool has_obj  = ((has | peer_has) & 1) != 0;

    const float m0 = half ? pm : m;   const int g0 = half ? peer_g : g;
    const float m1 = half ? m  : pm;  const int g1 = half ? g : peer_g;
    const int gnd = (m1 > m0) ? g1 : g0;           // lower index wins ties
    const float pg = p[10 + gnd];

    float pos_h = 0.0f;
    if (bi == half && has_obj) {
        const float dx = p[bo+0] - t[bo+0];
        const float dy = p[bo+1] - t[bo+1];
        pos_h = dx * dx + dy * dy;
    }

    const float cd = iou_own * pg - iou_own;
    const float w  = (bi == half) ? 1.0f : LAMBDA_NOOBJ;
    return cls + w * cd * cd + pos_h;
}

// full scalar cell loss (tail path only; unused for these shapes)
__device__ __forceinline__ float cell_loss_full(const float* p, const float* t)
{
    float iou[2];
    #pragma unroll
    for (int b = 0; b < 2; b++) {
        const float x1 = p[b*5+0], y1 = p[b*5+1], w1 = p[b*5+2], h1 = p[b*5+3];
        const float x2 = t[b*5+0], y2 = t[b*5+1], w2 = t[b*5+2], h2 = t[b*5+3];
        const float tlx = fmaxf(x1 - w1 * 0.5f, x2 - w2 * 0.5f);
        const float tly = fmaxf(y1 - h1 * 0.5f, y2 - h2 * 0.5f);
        const float brx = fminf(x1 + w1 * 0.5f, x2 + w2 * 0.5f);
        const float bry = fminf(y1 + h1 * 0.5f, y2 + h2 * 0.5f);
        const float iw = fmaxf(0.0f, brx - tlx);
        const float ih = fmaxf(0.0f, bry - tly);
        const float inter = iw * ih;
        iou[b] = inter / (w1 * h1 + w2 * h2 - inter);
    }
    const int bi = (iou[1] > iou[0]) ? 1 : 0;
    float cls = 0.0f, maxtc = t[10];
    int gnd = 0; bool has_obj = false;
    #pragma unroll
    for (int j = 0; j < 20; j++) {
        const float pc = p[10 + j], tc = t[10 + j];
        const float d = pc - tc;
        cls += d * d;
        if (tc != 0.0f) has_obj = true;
        if (tc > maxtc) { maxtc = tc; gnd = j; }
    }
    const float pg = p[10 + gnd];
    const float dx = p[bi*5+0] - t[bi*5+0];
    const float dy = p[bi*5+1] - t[bi*5+1];
    const float pos = has_obj ? (dx * dx + dy * dy) : 0.0f;
    float conf = 0.0f;
    #pragma unroll
    for (int b = 0; b < 2; b++) {
        const float cd = iou[b] * pg - iou[b];
        const float w  = (b == bi) ? 1.0f : LAMBDA_NOOBJ;
        conf += w * cd * cd;
    }
    return pos + cls + conf;
}

__global__ __launch_bounds__(TPB) void yolo_loss_kernel(
    const float* __restrict__ preds,
    const float* __restrict__ targets,
    long long n_cells,
    unsigned int n_blocks,
    float invN,
    float* __restrict__ out)
{
    extern __shared__ __align__(128) float smem[];
    uint32_t sp_a[NSTAGE], st_a[NSTAGE], full_a[NSTAGE];
    {
        uint64_t* bars = reinterpret_cast<uint64_t*>(smem + NSTAGE * 2 * TILE_FLOATS);
        #pragma unroll
        for (int s = 0; s < NSTAGE; s++) {
            sp_a[s]   = smem_u32(smem + (2 * s)     * TILE_FLOATS);
            st_a[s]   = smem_u32(smem + (2 * s + 1) * TILE_FLOATS);
            full_a[s] = smem_u32(&bars[s]);
        }
    }

    const int tid  = threadIdx.x;
    const int cell = tid >> 1;          // 0..255
    const int half = tid & 1;
    const unsigned int bid  = blockIdx.x;
    const unsigned int grid = gridDim.x;

    const unsigned int num_full = (unsigned int)(n_cells / CPT);
    const unsigned int my_count =
        (num_full > bid) ? (num_full - 1u - bid) / grid + 1u : 0u;

    if (tid == 0) {
        #pragma unroll
        for (int s = 0; s < NSTAGE; s++)
            asm volatile("mbarrier.init.shared.b64 [%0], %1;"
                         :: "r"(full_a[s]), "r"(1u) : "memory");
        asm volatile("fence.proxy.async.shared::cta;" ::: "memory");
    }
    __syncthreads();   // barrier inits visible before TMA targets them / anyone waits

    // Prologue: stage s gets preds via TMA (thread 0) and targets via cp.async
    // (all threads). One commit group per stage, ALWAYS committed (possibly
    // empty) so group accounting stays exact: group g <-> stage g.
    for (unsigned int s = 0; s < NSTAGE; s++) {
        if (s < my_count) {
            const long long tile = (long long)(bid + s * grid);
            if (tid == 0) issue_preds_tma(full_a[s], sp_a[s], preds, tile);
            issue_targets_cpasync(st_a[s], targets, tile, tid);
        }
        asm volatile("cp.async.commit_group;" ::: "memory");
    }

    float loss = 0.0f;

    for (unsigned int j = 0; j < my_count; j++) {
        const unsigned int stage = j % NSTAGE;
        const uint32_t par = (j / NSTAGE) & 1u;

        // own cp.async group for stage j complete (groups j+1, j+2 may pend)
        asm volatile("cp.async.wait_group %0;" :: "n"(NSTAGE - 1) : "memory");
        // preds TMA for stage j complete
        mbar_wait(full_a[stage], par);
        // all threads' cp.asyncs for stage j complete + visible
        __syncthreads();

        loss += cell_loss_pair(
            reinterpret_cast<const float*>(smem) + (2 * stage)     * TILE_FLOATS + cell * DD,
            reinterpret_cast<const float*>(smem) + (2 * stage + 1) * TILE_FLOATS + cell * DD,
            half);

        __syncthreads();   // everyone done reading this stage's buffers

        // refill this stage with tile j+NSTAGE; always commit one group
        if (j + NSTAGE < my_count) {
            const long long tile = (long long)(bid + (j + NSTAGE) * grid);
            if (tid == 0) issue_preds_tma(full_a[stage], sp_a[stage], preds, tile);
            issue_targets_cpasync(st_a[stage], targets, tile, tid);
        }
        asm volatile("cp.async.commit_group;" ::: "memory");
    }

    // tail cells (n_cells % CPT) — block 0, direct gmem reads, scalar path
    const long long tail_start = (long long)num_full * CPT;
    if (bid == 0 && tail_start + tid < n_cells) {
        loss += cell_loss_full(preds   + (tail_start + tid) * DD,
                               targets + (tail_start + tid) * DD);
    }

    // block reduction: warp shuffle -> smem -> one double atomic per block
    #pragma unroll
    for (int o = 16; o > 0; o >>= 1)
        loss += __shfl_down_sync(0xffffffffu, loss, o);

    __shared__ float wsum[TPB / 32];
    __shared__ bool  is_last;
    if ((tid & 31) == 0) wsum[tid >> 5] = loss;
    __syncthreads();

    if (tid == 0) {
        float s = 0.0f;
        #pragma unroll
        for (int i = 0; i < TPB / 32; i++) s += wsum[i];
        atomicAdd(&g_acc, (double)s);
        __threadfence();
        const unsigned int prev = atomicAdd(&g_count, 1u);
        is_last = (prev == n_blocks - 1u);
    }
    __syncthreads();

    if (is_last && tid == 0) {
        out[0] = (float)(g_acc * (double)invN);
        g_acc   = 0.0;                // reset for next graph replay
        __threadfence();
        g_count = 0u;
    }
}

extern "C" void kernel_launch(void* const* d_in, const int* in_sizes, int n_in,
                              void* d_out, int out_size)
{
    const float* preds   = (const float*)d_in[0];
    const float* targets = (const float*)d_in[1];

    const long long n_cells = (long long)in_sizes[0] / DD;   // N*S*S
    const long long N = n_cells / 49;                         // S=7

    cudaFuncSetAttribute(yolo_loss_kernel,
                         cudaFuncAttributeMaxDynamicSharedMemorySize,
                         SMEM_DYN_BYTES);

    const unsigned int num_tiles = (unsigned int)((n_cells + CPT - 1) / CPT);
    unsigned int grid = 148u;                 // 1 block/SM (~184 KB smem each)
    if (grid > num_tiles) grid = num_tiles ? num_tiles : 1u;

    yolo_loss_kernel<<<grid, TPB, SMEM_DYN_BYTES>>>(preds, targets, n_cells, grid,
                                                    1.0f / (float)N, (float*)d_out);
}

// round 12
// speedup vs baseline: 1.0555x; 1.0208x over previous
#include <cuda_runtime.h>
#include <cstdint>

#define TPB  512       // threads per block (2 per cell)
#define CPT  256       // cells per tile
#define DD   30        // features per cell: B*5 + C
#define LAMBDA_NOOBJ 0.5f
#define NSTAGE 3

#define TILE_FLOATS (CPT * DD)            // 7680 floats per array per tile
#define TILE_BYTES  (TILE_FLOATS * 4)     // 30720 B
// dynamic smem: [ sp0|st0 | sp1|st1 | sp2|st2 | full[3] | tiles[3] ]
#define SMEM_DYN_BYTES (NSTAGE * 2 * TILE_BYTES + NSTAGE * 8 + NSTAGE * 4)

__device__ double       g_acc;
__device__ unsigned int g_count;
__device__ unsigned int g_next;   // dynamic tile queue head; reset by last block

__device__ __forceinline__ uint32_t smem_u32(const void* p) {
    uint32_t a;
    asm("{ .reg .u64 t; cvta.to.shared.u64 t, %1; cvt.u32.u64 %0, t; }"
        : "=r"(a) : "l"(p));
    return a;
}

__device__ __forceinline__ void mbar_wait(uint32_t mb, uint32_t parity) {
    uint32_t done;
    do {
        asm volatile(
            "{\n\t.reg .pred p;\n\t"
            "mbarrier.try_wait.parity.acquire.cta.shared::cta.b64 p, [%1], %2, 0x989680;\n\t"
            "selp.b32 %0, 1, 0, p;\n\t}"
            : "=r"(done) : "r"(mb), "r"(parity) : "memory");
    } while (!done);
}

__device__ __forceinline__ void issue_tile_copy(uint32_t mb_full,
                                                uint32_t sp_addr, uint32_t st_addr,
                                                const float* preds, const float* targets,
                                                long long tile)
{
    asm volatile("mbarrier.arrive.expect_tx.shared.b64 _, [%0], %1;"
                 :: "r"(mb_full), "r"(2u * TILE_BYTES) : "memory");
    asm volatile("cp.async.bulk.shared::cta.global.mbarrier::complete_tx::bytes "
                 "[%0], [%1], %2, [%3];"
                 :: "r"(sp_addr), "l"(preds + tile * (long long)TILE_FLOATS),
                    "r"((uint32_t)TILE_BYTES), "r"(mb_full) : "memory");
    asm volatile("cp.async.bulk.shared::cta.global.mbarrier::complete_tx::bytes "
                 "[%0], [%1], %2, [%3];"
                 :: "r"(st_addr), "l"(targets + tile * (long long)TILE_FLOATS),
                    "r"((uint32_t)TILE_BYTES), "r"(mb_full) : "memory");
}

// Claim next tile (thread 0 only): record index in smem, then either issue the
// TMA pair or complete the barrier with a plain arrive (null stage). The smem
// write happens-before the releasing arrive, so consumers reading after their
// acquiring wait see the correct tile index.
__device__ __forceinline__ void claim_and_issue(volatile int* tiles_s, int stage,
                                                uint32_t mb_full,
                                                uint32_t sp_addr, uint32_t st_addr,
                                                const float* preds, const float* targets,
                                                unsigned int num_tiles)
{
    const unsigned int t = atomicAdd(&g_next, 1u);
    tiles_s[stage] = (int)t;
    if (t < num_tiles) {
        issue_tile_copy(mb_full, sp_addr, st_addr, preds, targets, (long long)t);
    } else {
        asm volatile("mbarrier.arrive.shared.b64 _, [%0];" :: "r"(mb_full) : "memory");
    }
}

// Pair-split cell loss: lanes (2k, 2k+1) cooperate on cell k. Uniform control
// flow; returns this thread's ADDITIVE contribution.
__device__ __forceinline__ float cell_loss_pair(const float* __restrict__ p,
                                                const float* __restrict__ t,
                                                int half)
{
    const int bo = half * 5;
    const float x1 = p[bo+0], y1 = p[bo+1], w1 = p[bo+2], h1 = p[bo+3];
    const float x2 = t[bo+0], y2 = t[bo+1], w2 = t[bo+2], h2 = t[bo+3];
    const float tlx = fmaxf(x1 - w1 * 0.5f, x2 - w2 * 0.5f);
    const float tly = fmaxf(y1 - h1 * 0.5f, y2 - h2 * 0.5f);
    const float brx = fminf(x1 + w1 * 0.5f, x2 + w2 * 0.5f);
    const float bry = fminf(y1 + h1 * 0.5f, y2 + h2 * 0.5f);
    const float iw = fmaxf(0.0f, brx - tlx);
    const float ih = fmaxf(0.0f, bry - tly);
    const float inter = iw * ih;
    const float iou_own = inter / (w1 * h1 + w2 * h2 - inter);

    const float iou_peer = __shfl_xor_sync(0xffffffffu, iou_own, 1);
    const float iou0 = half ? iou_peer : iou_own;
    const float iou1 = half ? iou_own  : iou_peer;
    const int bi = (iou1 > iou0) ? 1 : 0;          // first-max tie break

    const int cb = 10 + half * 10;
    float cls = 0.0f;
    float m = t[cb];
    int g = half * 10;
    int has = 0;
    #pragma unroll
    for (int j = 0; j < 10; j++) {
        const float pc = p[cb + j];
        const float tc = t[cb + j];
        const float d = pc - tc;
        cls += d * d;
        has |= (tc != 0.0f) ? 1 : 0;
        if (tc > m) { m = tc; g = half * 10 + j; }
    }
    const float pm  = __shfl_xor_sync(0xffffffffu, m, 1);
    const int   pkt = __shfl_xor_sync(0xffffffffu, g | (has << 8), 1);
    const int  peer_g   = pkt & 0xff;
    const int  peer_has = pkt >> 8;
    const bool has_obj  = ((has | peer_has) & 1) != 0;

    const float m0 = half ? pm : m;   const int g0 = half ? peer_g : g;
    const float m1 = half ? m  : pm;  const int g1 = half ? g : peer_g;
    const int gnd = (m1 > m0) ? g1 : g0;           // lower index wins ties
    const float pg = p[10 + gnd];

    float pos_h = 0.0f;
    if (bi == half && has_obj) {
        const float dx = p[bo+0] - t[bo+0];
        const float dy = p[bo+1] - t[bo+1];
        pos_h = dx * dx + dy * dy;
    }

    const float cd = iou_own * pg - iou_own;
    const float w  = (bi == half) ? 1.0f : LAMBDA_NOOBJ;
    return cls + w * cd * cd + pos_h;
}

// full scalar cell loss (tail path only; unused for these shapes)
__device__ __forceinline__ float cell_loss_full(const float* p, const float* t)
{
    float iou[2];
    #pragma unroll
    for (int b = 0; b < 2; b++) {
        const float x1 = p[b*5+0], y1 = p[b*5+1], w1 = p[b*5+2], h1 = p[b*5+3];
        const float x2 = t[b*5+0], y2 = t[b*5+1], w2 = t[b*5+2], h2 = t[b*5+3];
        const float tlx = fmaxf(x1 - w1 * 0.5f, x2 - w2 * 0.5f);
        const float tly = fmaxf(y1 - h1 * 0.5f, y2 - h2 * 0.5f);
        const float brx = fminf(x1 + w1 * 0.5f, x2 + w2 * 0.5f);
        const float bry = fminf(y1 + h1 * 0.5f, y2 + h2 * 0.5f);
        const float iw = fmaxf(0.0f, brx - tlx);
        const float ih = fmaxf(0.0f, bry - tly);
        const float inter = iw * ih;
        iou[b] = inter / (w1 * h1 + w2 * h2 - inter);
    }
    const int bi = (iou[1] > iou[0]) ? 1 : 0;
    float cls = 0.0f, maxtc = t[10];
    int gnd = 0; bool has_obj = false;
    #pragma unroll
    for (int j = 0; j < 20; j++) {
        const float pc = p[10 + j], tc = t[10 + j];
        const float d = pc - tc;
        cls += d * d;
        if (tc != 0.0f) has_obj = true;
        if (tc > maxtc) { maxtc = tc; gnd = j; }
    }
    const float pg = p[10 + gnd];
    const float dx = p[bi*5+0] - t[bi*5+0];
    const float dy = p[bi*5+1] - t[bi*5+1];
    const float pos = has_obj ? (dx * dx + dy * dy) : 0.0f;
    float conf = 0.0f;
    #pragma unroll
    for (int b = 0; b < 2; b++) {
        const float cd = iou[b] * pg - iou[b];
        const float w  = (b == bi) ? 1.0f : LAMBDA_NOOBJ;
        conf += w * cd * cd;
    }
    return pos + cls + conf;
}

__global__ __launch_bounds__(TPB) void yolo_loss_kernel(
    const float* __restrict__ preds,
    const float* __restrict__ targets,
    long long n_cells,
    unsigned int n_blocks,
    float invN,
    float* __restrict__ out)
{
    extern __shared__ __align__(128) float smem[];
    uint32_t sp_a[NSTAGE], st_a[NSTAGE], full_a[NSTAGE];
    volatile int* tiles_s;
    {
        uint64_t* bars = reinterpret_cast<uint64_t*>(smem + NSTAGE * 2 * TILE_FLOATS);
        #pragma unroll
        for (int s = 0; s < NSTAGE; s++) {
            sp_a[s]   = smem_u32(smem + (2 * s)     * TILE_FLOATS);
            st_a[s]   = smem_u32(smem + (2 * s + 1) * TILE_FLOATS);
            full_a[s] = smem_u32(&bars[s]);
        }
        tiles_s = reinterpret_cast<volatile int*>(bars + NSTAGE);
    }

    const int tid  = threadIdx.x;
    const int cell = tid >> 1;          // 0..255
    const int half = tid & 1;

    const unsigned int num_tiles = (unsigned int)(n_cells / CPT);

    if (tid == 0) {
        #pragma unroll
        for (int s = 0; s < NSTAGE; s++)
            asm volatile("mbarrier.init.shared.b64 [%0], %1;"
                         :: "r"(full_a[s]), "r"(1u) : "memory");
        asm volatile("fence.proxy.async.shared::cta;" ::: "memory");
        #pragma unroll
        for (int s = 0; s < NSTAGE; s++)
            claim_and_issue(tiles_s, s, full_a[s], sp_a[s], st_a[s],
                            preds, targets, num_tiles);
    }
    __syncthreads();   // barrier inits + prologue visible

    float loss = 0.0f;

    for (unsigned int j = 0; ; j++) {
        const unsigned int stage = j % NSTAGE;
        const uint32_t par = (j / NSTAGE) & 1u;

        mbar_wait(full_a[stage], par);

        const int tile = tiles_s[stage];          // valid: released by arrive
        if ((unsigned int)tile >= num_tiles) break;   // uniform across block

        loss += cell_loss_pair(
            reinterpret_cast<const float*>(smem) + (2 * stage)     * TILE_FLOATS + cell * DD,
            reinterpret_cast<const float*>(smem) + (2 * stage + 1) * TILE_FLOATS + cell * DD,
            half);

        __syncthreads();   // everyone done reading this stage's buffers

        if (tid == 0)
            claim_and_issue(tiles_s, stage, full_a[stage], sp_a[stage], st_a[stage],
                            preds, targets, num_tiles);
    }

    // tail cells (n_cells % CPT) — block 0, direct gmem reads, scalar path
    const long long tail_start = (long long)num_tiles * CPT;
    if (blockIdx.x == 0 && tail_start + tid < n_cells) {
        loss += cell_loss_full(preds   + (tail_start + tid) * DD,
                               targets + (tail_start + tid) * DD);
    }

    // block reduction: warp shuffle -> smem -> one double atomic per block
    #pragma unroll
    for (int o = 16; o > 0; o >>= 1)
        loss += __shfl_down_sync(0xffffffffu, loss, o);

    __shared__ float wsum[TPB / 32];
    __shared__ bool  is_last;
    if ((tid & 31) == 0) wsum[tid >> 5] = loss;
    __syncthreads();

    if (tid == 0) {
        float s = 0.0f;
        #pragma unroll
        for (int i = 0; i < TPB / 32; i++) s += wsum[i];
        atomicAdd(&g_acc, (double)s);
        __threadfence();
        const unsigned int prev = atomicAdd(&g_count, 1u);
        is_last = (prev == n_blocks - 1u);
    }
    __syncthreads();

    if (is_last && tid == 0) {
        out[0] = (float)(g_acc * (double)invN);
        // reset globals for next graph replay (runs alone; kernel-ordered)
        g_acc   = 0.0;
        g_next  = 0u;
        __threadfence();
        g_count = 0u;
    }
}

extern "C" void kernel_launch(void* const* d_in, const int* in_sizes, int n_in,
                              void* d_out, int out_size)
{
    const float* preds   = (const float*)d_in[0];
    const float* targets = (const float*)d_in[1];

    const long long n_cells = (long long)in_sizes[0] / DD;   // N*S*S
    const long long N = n_cells / 49;                         // S=7

    cudaFuncSetAttribute(yolo_loss_kernel,
                         cudaFuncAttributeMaxDynamicSharedMemorySize,
                         SMEM_DYN_BYTES);

    const unsigned int num_tiles = (unsigned int)((n_cells + CPT - 1) / CPT);
    unsigned int grid = 148u;                 // 1 block/SM (~184 KB smem each)
    if (grid > num_tiles) grid = num_tiles ? num_tiles : 1u;

    yolo_loss_kernel<<<grid, TPB, SMEM_DYN_BYTES>>>(preds, targets, n_cells, grid,
                                                    1.0f / (float)N, (float*)d_out);
}